// round 2
// baseline (speedup 1.0000x reference)
#include <cuda_runtime.h>

// Conv 3x3 (64->128) + reflect pad 1 + folded BN + LeakyReLU(0.01) + int mask
// x: (1,64,512,512) f32 | W: (128,64,3,3) f32 | gamma,beta,mean,var: (128) f32
// mask: (1,128,512,512) i32 | out: (1,128,512,512) f32

#define Hd   512
#define Wd   512
#define Cin  64
#define Kout 128
#define TH   16      // tile height (output rows per block)
#define TW   64      // tile width  (output cols per block)
#define OCB  16      // output channels per block
#define STR  68      // smem padded row stride in floats (>= TW+2, mult of 4)

__device__ __forceinline__ unsigned long long pack2(float lo, float hi) {
    unsigned long long r;
    asm("mov.b64 %0, {%1, %2};" : "=l"(r) : "f"(lo), "f"(hi));
    return r;
}
__device__ __forceinline__ void unpack2(unsigned long long v, float& lo, float& hi) {
    asm("mov.b64 {%0, %1}, %2;" : "=f"(lo), "=f"(hi) : "l"(v));
}
__device__ __forceinline__ void fma2(unsigned long long& acc,
                                     unsigned long long a, unsigned long long b) {
    // packed f32x2 FMA: acc = a*b + acc  (lane-wise on the two f32 halves)
    asm("fma.rn.f32x2 %0, %1, %2, %3;" : "=l"(acc) : "l"(a), "l"(b), "l"(acc));
}

__global__ void __launch_bounds__(256, 2)
conv_bn_lrelu_mask(const float* __restrict__ x,
                   const float* __restrict__ Wt,
                   const float* __restrict__ gamma,
                   const float* __restrict__ beta,
                   const float* __restrict__ mean,
                   const float* __restrict__ var,
                   const int*   __restrict__ mask,
                   float*       __restrict__ out)
{
    __shared__ __align__(16) float s_in[18 * STR];       // input tile + halo, 1 channel
    __shared__ __align__(16) float s_w[9][OCB];          // [tap][oc] -> oc-pairs contiguous
    __shared__ float s_scale[OCB], s_shift[OCB];

    const int tid  = threadIdx.x;
    const int tx   = tid & 15;        // 16 column groups of 4 px
    const int ty   = tid >> 4;        // 16 rows
    const int col0 = blockIdx.x * TW;
    const int row0 = blockIdx.y * TH;
    const int oc0  = blockIdx.z * OCB;

    if (tid < OCB) {
        const float g  = gamma[oc0 + tid];
        const float vv = var[oc0 + tid];
        const float sc = g * rsqrtf(vv + 1e-5f);
        s_scale[tid] = sc;
        s_shift[tid] = beta[oc0 + tid] - mean[oc0 + tid] * sc;
    }

    // acc[p][op]: pixel p (0..3), oc-pair op (lo = oc 2*op, hi = oc 2*op+1)
    unsigned long long acc[4][OCB / 2];
    #pragma unroll
    for (int p = 0; p < 4; ++p)
        #pragma unroll
        for (int o = 0; o < OCB / 2; ++o)
            acc[p][o] = 0ull;   // bit pattern of (+0.f, +0.f)

    for (int c = 0; c < Cin; ++c) {
        __syncthreads();   // protect smem reuse from previous iteration's readers

        // --- stage weights for this input channel: s_w[tap][oc] ---
        if (tid < 9 * OCB) {
            const int tap = tid >> 4;      // 0..8
            const int oc  = tid & 15;      // 0..15
            s_w[tap][oc] = Wt[((oc0 + oc) * Cin + c) * 9 + tap];
        }

        // --- stage input tile (18 x 66) with reflect halo ---
        const float* __restrict__ xc = x + c * (Hd * Wd);
        for (int idx = tid; idx < 18 * 66; idx += 256) {
            const int r  = idx / 66;
            const int cc = idx - r * 66;
            int gr = row0 - 1 + r;
            gr = (gr < 0) ? -gr : ((gr >= Hd) ? (2 * Hd - 2 - gr) : gr);
            int gc = col0 - 1 + cc;
            gc = (gc < 0) ? -gc : ((gc >= Wd) ? (2 * Wd - 2 - gc) : gc);
            s_in[r * STR + cc] = xc[gr * Wd + gc];
        }
        __syncthreads();

        // --- per-thread: 3 rows x 6 cols of input, duplicate-packed ---
        unsigned long long vd[3][6];
        #pragma unroll
        for (int r = 0; r < 3; ++r) {
            const float* p4 = &s_in[(ty + r) * STR + (tx << 2)];
            const float4 a = *(const float4*)(p4);
            const float2 b = *(const float2*)(p4 + 4);
            vd[r][0] = pack2(a.x, a.x);
            vd[r][1] = pack2(a.y, a.y);
            vd[r][2] = pack2(a.z, a.z);
            vd[r][3] = pack2(a.w, a.w);
            vd[r][4] = pack2(b.x, b.x);
            vd[r][5] = pack2(b.y, b.y);
        }

        // --- 8 oc-pairs x 4 px x 9 taps of packed FMA ---
        #pragma unroll
        for (int op = 0; op < OCB / 2; ++op) {
            unsigned long long w[9];
            #pragma unroll
            for (int t = 0; t < 9; ++t)
                w[t] = *(const unsigned long long*)&s_w[t][op * 2];
            #pragma unroll
            for (int p = 0; p < 4; ++p)
                #pragma unroll
                for (int r = 0; r < 3; ++r)
                    #pragma unroll
                    for (int dx = 0; dx < 3; ++dx)
                        fma2(acc[p][op], vd[r][p + dx], w[r * 3 + dx]);
        }
    }

    // ---------------- epilogue: BN + LeakyReLU + mask, float4 stores -------
    const int orow = row0 + ty;
    const int ocol = col0 + (tx << 2);

    #pragma unroll
    for (int op = 0; op < OCB / 2; ++op) {
        float ev[4], ov[4];
        #pragma unroll
        for (int p = 0; p < 4; ++p)
            unpack2(acc[p][op], ev[p], ov[p]);

        #pragma unroll
        for (int half = 0; half < 2; ++half) {
            const int   oc = op * 2 + half;
            const float sc = s_scale[oc];
            const float sh = s_shift[oc];
            const int base = ((oc0 + oc) * Hd + orow) * Wd + ocol;
            const int4 m = *(const int4*)(mask + base);

            float y0 = fmaf(half ? ov[0] : ev[0], sc, sh);
            float y1 = fmaf(half ? ov[1] : ev[1], sc, sh);
            float y2 = fmaf(half ? ov[2] : ev[2], sc, sh);
            float y3 = fmaf(half ? ov[3] : ev[3], sc, sh);
            y0 = (y0 >= 0.f) ? y0 : 0.01f * y0;
            y1 = (y1 >= 0.f) ? y1 : 0.01f * y1;
            y2 = (y2 >= 0.f) ? y2 : 0.01f * y2;
            y3 = (y3 >= 0.f) ? y3 : 0.01f * y3;

            float4 r;
            r.x = y0 * (float)m.x;
            r.y = y1 * (float)m.y;
            r.z = y2 * (float)m.z;
            r.w = y3 * (float)m.w;
            *(float4*)(out + base) = r;
        }
    }
}

extern "C" void kernel_launch(void* const* d_in, const int* in_sizes, int n_in,
                              void* d_out, int out_size)
{
    const float* x     = (const float*)d_in[0];
    const float* Wt    = (const float*)d_in[1];
    const float* gamma = (const float*)d_in[2];
    const float* beta  = (const float*)d_in[3];
    const float* mean  = (const float*)d_in[4];
    const float* var   = (const float*)d_in[5];
    const int*   mask  = (const int*)d_in[6];
    float*       out   = (float*)d_out;

    dim3 grid(Wd / TW, Hd / TH, Kout / OCB);   // (8, 32, 8)
    conv_bn_lrelu_mask<<<grid, 256>>>(x, Wt, gamma, beta, mean, var, mask, out);
}

// round 4
// speedup vs baseline: 4.6128x; 4.6128x over previous
#include <cuda_runtime.h>
#include <cuda_bf16.h>
#include <cstdint>

#define Hh 512
#define Ww 512
#define CIN 64
#define KOC 128
#define HWSZ (Hh*Ww)
#define NT 9

#define AHI 0
#define ALO 16384
#define WHI 32768
#define WLO 49152
#define SCL 65536
#define SHF 66048
#define SMEM_TOTAL 66560

#define SWZ(o) ((o) ^ ((((uint32_t)(o))>>3)&0x70))

__device__ __align__(16) unsigned char WbHi[NT*16384];
__device__ __align__(16) unsigned char WbLo[NT*16384];

static __device__ __forceinline__ uint32_t s2u(const void* p){
    uint32_t a;
    asm("{ .reg .u64 t; cvta.to.shared.u64 t, %1; cvt.u32.u64 %0, t; }":"=r"(a):"l"(p));
    return a;
}
static __device__ __forceinline__ void ldsm4(uint32_t addr,
        uint32_t &r0, uint32_t &r1, uint32_t &r2, uint32_t &r3){
    asm volatile("ldmatrix.sync.aligned.m8n8.x4.shared.b16 {%0,%1,%2,%3}, [%4];"
        : "=r"(r0),"=r"(r1),"=r"(r2),"=r"(r3) : "r"(addr));
}
static __device__ __forceinline__ void hmma(float* c,
        uint32_t a0,uint32_t a1,uint32_t a2,uint32_t a3,
        uint32_t b0,uint32_t b1){
    asm volatile("mma.sync.aligned.m16n8k16.row.col.f32.bf16.bf16.f32 "
        "{%0,%1,%2,%3}, {%4,%5,%6,%7}, {%8,%9}, {%0,%1,%2,%3};"
        : "+f"(c[0]),"+f"(c[1]),"+f"(c[2]),"+f"(c[3])
        : "r"(a0),"r"(a1),"r"(a2),"r"(a3),"r"(b0),"r"(b1));
}

// ---------- prep: split W into bf16 hi/lo, pre-swizzled K-major SW128 tiles ----------
__global__ void prep_w(const float* __restrict__ Wt){
    int idx = blockIdx.x * blockDim.x + threadIdx.x;   // 9*128*64
    if (idx >= NT*KOC*CIN) return;
    int t   = idx >> 13;
    int rem = idx & 8191;
    int n   = rem >> 6;
    int kk  = rem & 63;
    float v = Wt[(n*CIN + kk)*9 + t];
    __nv_bfloat16 hi = __float2bfloat16_rn(v);
    __nv_bfloat16 lo = __float2bfloat16_rn(v - __bfloat162float(hi));
    uint32_t off = SWZ((uint32_t)(n*128 + kk*2));
    *(__nv_bfloat16*)(WbHi + t*16384 + off) = hi;
    *(__nv_bfloat16*)(WbLo + t*16384 + off) = lo;
}

// ---------- main fused kernel: implicit-GEMM via mma.sync bf16 3-pass ----------
__global__ void __launch_bounds__(256,2)
conv_mma(const float* __restrict__ x,
         const float* __restrict__ gamma, const float* __restrict__ beta,
         const float* __restrict__ mean,  const float* __restrict__ var,
         const int*   __restrict__ mask,  float* __restrict__ out)
{
    extern __shared__ __align__(1024) char sm[];
    const uint32_t smb = s2u(sm);

    const int tid  = threadIdx.x;
    const int w    = tid >> 5;
    const int lane = tid & 31;
    const int wm   = w >> 2;           // 0..1 : m offset wm*64
    const int wn   = w & 3;            // 0..3 : n offset wn*32

    float* s_scale = (float*)(sm + SCL);
    float* s_shift = (float*)(sm + SHF);
    if (tid < KOC) {
        float sc = gamma[tid] * rsqrtf(var[tid] + 1e-5f);
        s_scale[tid] = sc;
        s_shift[tid] = beta[tid] - mean[tid] * sc;
    }

    const int bid = blockIdx.x;        // 2048
    const int r   = bid >> 2;          // image row
    const int ct  = bid & 3;           // 128-col tile
    const int col0 = ct * 128;

    float acc[4][4][4];
    #pragma unroll
    for (int m = 0; m < 4; ++m)
        #pragma unroll
        for (int n = 0; n < 4; ++n)
            #pragma unroll
            for (int e = 0; e < 4; ++e) acc[m][n][e] = 0.f;

    // precompute ldmatrix lane geometry
    const int jj = lane >> 3, rr = lane & 7;
    // A: row = msub*16 + (jj&1)*8 + rr ; col = ks*32 + (jj>>1)*16
    const int a_row_l = ((jj & 1) << 3) + rr;
    const int a_col_l = (jj >> 1) << 4;
    // B: row = np*16 + (jj>>1)*8 + rr ; col = ks*32 + (jj&1)*16
    const int b_row_l = ((jj >> 1) << 3) + rr;
    const int b_col_l = (jj & 1) << 4;

    for (int ch = 0; ch < NT; ++ch) {
        const int dy = ch / 3 - 1;
        const int dx = ch % 3 - 1;
        int srow = r + dy;
        srow = (srow < 0) ? -srow : ((srow > Hh-1) ? (2*Hh-2 - srow) : srow);

        __syncthreads();   // previous compute finished reading smem

        // ---- stage A (im2col gather, bf16 hi/lo), warp w -> channels w*8..w*8+7 ----
        {
            int colv[4];
            #pragma unroll
            for (int i = 0; i < 4; ++i) {
                int cc = col0 + dx + lane + 32*i;
                colv[i] = (cc < 0) ? -cc : ((cc > Ww-1) ? (2*Ww-2 - cc) : cc);
            }
            float v[8][4];
            #pragma unroll
            for (int j = 0; j < 8; ++j) {
                const float* xp = x + ((w*8 + j)*Hh + srow)*Ww;
                #pragma unroll
                for (int i = 0; i < 4; ++i) v[j][i] = __ldg(xp + colv[i]);
            }
            #pragma unroll
            for (int i = 0; i < 4; ++i) {
                const int m = lane + 32*i;
                uint32_t hw4[4], lw4[4];
                #pragma unroll
                for (int q = 0; q < 4; ++q) {
                    float a  = v[2*q][i], b = v[2*q+1][i];
                    __nv_bfloat162 hp = __floats2bfloat162_rn(a, b);
                    float ra = a - __bfloat162float(hp.x);
                    float rb = b - __bfloat162float(hp.y);
                    __nv_bfloat162 lp = __floats2bfloat162_rn(ra, rb);
                    hw4[q] = *(uint32_t*)&hp;
                    lw4[q] = *(uint32_t*)&lp;
                }
                const uint32_t off = SWZ((uint32_t)(m*128 + w*16));
                *(uint4*)(sm + AHI + off) = make_uint4(hw4[0],hw4[1],hw4[2],hw4[3]);
                *(uint4*)(sm + ALO + off) = make_uint4(lw4[0],lw4[1],lw4[2],lw4[3]);
            }
        }
        // ---- stage W (pre-swizzled linear copy) ----
        {
            const uint4* sh = (const uint4*)(WbHi + ch*16384);
            const uint4* sl = (const uint4*)(WbLo + ch*16384);
            uint4* dh = (uint4*)(sm + WHI);
            uint4* dl = (uint4*)(sm + WLO);
            #pragma unroll
            for (int p = 0; p < 4; ++p) {
                dh[tid + p*256] = sh[tid + p*256];
                dl[tid + p*256] = sl[tid + p*256];
            }
        }
        __syncthreads();

        // ---- compute: 4 k16 steps ----
        #pragma unroll
        for (int ks = 0; ks < 4; ++ks) {
            const int kbyte = ks*32;
            uint32_t bh[8], bl[8];
            #pragma unroll
            for (int np = 0; np < 2; ++np) {
                const int brow = wn*32 + np*16 + b_row_l;
                const uint32_t boff = SWZ((uint32_t)(brow*128 + kbyte + b_col_l));
                ldsm4(smb + WHI + boff, bh[np*4+0], bh[np*4+1], bh[np*4+2], bh[np*4+3]);
                ldsm4(smb + WLO + boff, bl[np*4+0], bl[np*4+1], bl[np*4+2], bl[np*4+3]);
            }
            #pragma unroll
            for (int msub = 0; msub < 4; ++msub) {
                const int arow = wm*64 + msub*16 + a_row_l;
                const uint32_t aoff = SWZ((uint32_t)(arow*128 + kbyte + a_col_l));
                uint32_t ah[4], al[4];
                ldsm4(smb + AHI + aoff, ah[0], ah[1], ah[2], ah[3]);
                ldsm4(smb + ALO + aoff, al[0], al[1], al[2], al[3]);
                #pragma unroll
                for (int nsub = 0; nsub < 4; ++nsub) {
                    float* c = acc[msub][nsub];
                    hmma(c, ah[0],ah[1],ah[2],ah[3], bh[nsub*2], bh[nsub*2+1]); // hi*hi
                    hmma(c, ah[0],ah[1],ah[2],ah[3], bl[nsub*2], bl[nsub*2+1]); // hi*lo
                    hmma(c, al[0],al[1],al[2],al[3], bh[nsub*2], bh[nsub*2+1]); // lo*hi
                }
            }
        }
    }

    // ---------------- epilogue: BN + LeakyReLU + mask ----------------
    const int mrow = lane >> 2;
    const int ncol = (lane & 3) << 1;
    #pragma unroll
    for (int msub = 0; msub < 4; ++msub) {
        const int pix0 = r*Ww + col0 + wm*64 + msub*16 + mrow;
        #pragma unroll
        for (int nsub = 0; nsub < 4; ++nsub) {
            const int oc0 = wn*32 + nsub*8 + ncol;
            #pragma unroll
            for (int h = 0; h < 2; ++h) {
                const int pix = pix0 + h*8;
                #pragma unroll
                for (int e = 0; e < 2; ++e) {
                    const int oc = oc0 + e;
                    float y = fmaf(acc[msub][nsub][h*2+e], s_scale[oc], s_shift[oc]);
                    y = (y >= 0.f) ? y : 0.01f * y;
                    const int base = oc*HWSZ + pix;
                    out[base] = y * (float)mask[base];
                }
            }
        }
    }
}

extern "C" void kernel_launch(void* const* d_in, const int* in_sizes, int n_in,
                              void* d_out, int out_size)
{
    const float* x     = (const float*)d_in[0];
    const float* Wt    = (const float*)d_in[1];
    const float* gamma = (const float*)d_in[2];
    const float* beta  = (const float*)d_in[3];
    const float* mean  = (const float*)d_in[4];
    const float* var   = (const float*)d_in[5];
    const int*   mask  = (const int*)d_in[6];
    float*       out   = (float*)d_out;

    cudaFuncSetAttribute(conv_mma, cudaFuncAttributeMaxDynamicSharedMemorySize, SMEM_TOTAL);

    prep_w<<<(NT*KOC*CIN + 255)/256, 256>>>(Wt);
    conv_mma<<<2048, 256, SMEM_TOTAL>>>(x, gamma, beta, mean, var, mask, out);
}

// round 7
// speedup vs baseline: 4.7835x; 1.0370x over previous
#include <cuda_runtime.h>
#include <cuda_bf16.h>
#include <cstdint>

#define Hh 512
#define Ww 512
#define CIN 64
#define KOC 128
#define HWSZ (Hh*Ww)
#define NT 9

#define SWZ(o) ((o) ^ ((((uint32_t)(o))>>3)&0x70))

// ---- dynamic smem layout ----
#define SCL    0
#define SHF    512
#define ABASE  1024
#define AROWS  136
#define ABUFSZ (AROWS*128)                       // 17408
#define ABUF(dy,p) (ABASE + ((dy)*2+(p))*ABUFSZ) // 6 buffers: (dy 0..2) x (hi,lo)
#define WBASE  (ABASE + 6*ABUFSZ)                // 105472
#define WBUF(b) (WBASE + (b)*32768)              // hi @ +0 (16KB), lo @ +16384
#define SMEM_TOTAL (WBASE + 2*32768)             // 171008

__device__ __align__(16) unsigned char WbHi[NT*16384];
__device__ __align__(16) unsigned char WbLo[NT*16384];

static __device__ __forceinline__ uint32_t s2u(const void* p){
    uint32_t a;
    asm("{ .reg .u64 t; cvta.to.shared.u64 t, %1; cvt.u32.u64 %0, t; }":"=r"(a):"l"(p));
    return a;
}
static __device__ __forceinline__ void ldsm4(uint32_t addr,
        uint32_t &r0, uint32_t &r1, uint32_t &r2, uint32_t &r3){
    asm volatile("ldmatrix.sync.aligned.m8n8.x4.shared.b16 {%0,%1,%2,%3}, [%4];"
        : "=r"(r0),"=r"(r1),"=r"(r2),"=r"(r3) : "r"(addr));
}
static __device__ __forceinline__ void hmma(float* c,
        uint32_t a0,uint32_t a1,uint32_t a2,uint32_t a3,
        uint32_t b0,uint32_t b1){
    asm volatile("mma.sync.aligned.m16n8k16.row.col.f32.bf16.bf16.f32 "
        "{%0,%1,%2,%3}, {%4,%5,%6,%7}, {%8,%9}, {%0,%1,%2,%3};"
        : "+f"(c[0]),"+f"(c[1]),"+f"(c[2]),"+f"(c[3])
        : "r"(a0),"r"(a1),"r"(a2),"r"(a3),"r"(b0),"r"(b1));
}
static __device__ __forceinline__ void cpasync16(uint32_t daddr, const void* g){
    asm volatile("cp.async.cg.shared.global [%0], [%1], 16;" :: "r"(daddr), "l"(g) : "memory");
}
static __device__ __forceinline__ void cpcommit(){
    asm volatile("cp.async.commit_group;" ::: "memory");
}
template<int N> static __device__ __forceinline__ void cpwait(){
    asm volatile("cp.async.wait_group %0;" :: "n"(N) : "memory");
}

// ---------- prep: split W into bf16 hi/lo, pre-swizzled K-major SW128 tiles ----------
__global__ void prep_w(const float* __restrict__ Wt){
    int idx = blockIdx.x * blockDim.x + threadIdx.x;   // 9*128*64
    if (idx >= NT*KOC*CIN) return;
    int t   = idx >> 13;
    int rem = idx & 8191;
    int n   = rem >> 6;
    int kk  = rem & 63;
    float v = Wt[(n*CIN + kk)*9 + t];
    __nv_bfloat16 hi = __float2bfloat16_rn(v);
    __nv_bfloat16 lo = __float2bfloat16_rn(v - __bfloat162float(hi));
    uint32_t off = SWZ((uint32_t)(n*128 + kk*2));
    *(__nv_bfloat16*)(WbHi + t*16384 + off) = hi;
    *(__nv_bfloat16*)(WbLo + t*16384 + off) = lo;
}

// ---------- main fused kernel ----------
__global__ void __launch_bounds__(256,1)
conv_mma(const float* __restrict__ x,
         const float* __restrict__ gamma, const float* __restrict__ beta,
         const float* __restrict__ mean,  const float* __restrict__ var,
         const int*   __restrict__ mask,  float* __restrict__ out)
{
    extern __shared__ __align__(1024) char sm[];
    const uint32_t smb = s2u(sm);

    const int tid  = threadIdx.x;
    const int w    = tid >> 5;
    const int lane = tid & 31;
    const int wm   = w >> 2;           // 0..1 : m offset wm*64
    const int wn   = w & 3;            // 0..3 : n offset wn*32

    float* s_scale = (float*)(sm + SCL);
    float* s_shift = (float*)(sm + SHF);
    if (tid < KOC) {
        float sc = gamma[tid] * rsqrtf(var[tid] + 1e-5f);
        s_scale[tid] = sc;
        s_shift[tid] = beta[tid] - mean[tid] * sc;
    }

    const int bid  = blockIdx.x;       // 2048
    const int r    = bid >> 2;         // image row
    const int col0 = (bid & 3) * 128;  // 128-col tile

    float acc[4][4][4];
    #pragma unroll
    for (int m = 0; m < 4; ++m)
        #pragma unroll
        for (int n = 0; n < 4; ++n)
            #pragma unroll
            for (int e = 0; e < 4; ++e) acc[m][n][e] = 0.f;

    // ldmatrix lane geometry
    const int jj = lane >> 3, rr = lane & 7;
    const int a_row_l = ((jj & 1) << 3) + rr;
    const int a_col_l = (jj >> 1) << 4;
    const int b_row_l = ((jj >> 1) << 3) + rr;
    const int b_col_l = (jj & 1) << 4;

    // ---- prologue: prefetch W tap 0 (async), stage persistent A (3 dy rows) ----
    {
        const uint32_t d = smb + WBUF(0);
        #pragma unroll
        for (int p = 0; p < 4; ++p) {
            cpasync16(d + (tid + p*256)*16,         (const char*)WbHi + (tid + p*256)*16);
            cpasync16(d + 16384 + (tid + p*256)*16, (const char*)WbLo + (tid + p*256)*16);
        }
        cpcommit();
    }

    // persistent A: buffer row i <-> image column col0-1+i (reflected), i in [0,130)
    #pragma unroll
    for (int dy = 0; dy < 3; ++dy) {
        int srow = r + dy - 1;
        srow = (srow < 0) ? -srow : ((srow > Hh-1) ? (2*Hh-2 - srow) : srow);
        const float* xrow = x + (size_t)srow * Ww;
        #pragma unroll
        for (int ii = 0; ii < 5; ++ii) {
            const int ipix = lane + 32*ii;
            if (ipix < 130) {
                int cc = col0 - 1 + ipix;
                cc = (cc < 0) ? -cc : ((cc > Ww-1) ? (2*Ww-2 - cc) : cc);
                float v[8];
                #pragma unroll
                for (int j = 0; j < 8; ++j)
                    v[j] = __ldg(xrow + (size_t)(w*8 + j) * HWSZ + cc);
                uint32_t hw4[4], lw4[4];
                #pragma unroll
                for (int q = 0; q < 4; ++q) {
                    float a = v[2*q], b = v[2*q+1];
                    __nv_bfloat162 hp = __floats2bfloat162_rn(a, b);
                    float ra = a - __bfloat162float(hp.x);
                    float rb = b - __bfloat162float(hp.y);
                    __nv_bfloat162 lp = __floats2bfloat162_rn(ra, rb);
                    hw4[q] = *(uint32_t*)&hp;
                    lw4[q] = *(uint32_t*)&lp;
                }
                const uint32_t off = SWZ((uint32_t)(ipix*128 + w*16));
                *(uint4*)(sm + ABUF(dy,0) + off) = make_uint4(hw4[0],hw4[1],hw4[2],hw4[3]);
                *(uint4*)(sm + ABUF(dy,1) + off) = make_uint4(lw4[0],lw4[1],lw4[2],lw4[3]);
            }
        }
    }

    // ---- main loop over 9 taps, W double-buffered via cp.async ----
    for (int ch = 0; ch < NT; ++ch) {
        __syncthreads();     // compute(ch-1) done everywhere; A staging visible at ch=0

        if (ch + 1 < NT) {   // prefetch W(ch+1) into the other buffer
            const uint32_t d = smb + WBUF((ch+1) & 1);
            const char* sh = (const char*)WbHi + (ch+1)*16384;
            const char* sl = (const char*)WbLo + (ch+1)*16384;
            #pragma unroll
            for (int p = 0; p < 4; ++p) {
                cpasync16(d + (tid + p*256)*16,         sh + (tid + p*256)*16);
                cpasync16(d + 16384 + (tid + p*256)*16, sl + (tid + p*256)*16);
            }
            cpcommit();
            cpwait<1>();     // W(ch) has landed
        } else {
            cpwait<0>();
        }
        __syncthreads();     // W(ch) visible to all warps

        const int dyi   = ch / 3;
        const int rowoff= (ch % 3);          // dx+1
        const uint32_t wb  = smb + WBUF(ch & 1);
        const uint32_t ahi = smb + ABUF(dyi, 0);
        const uint32_t alo = smb + ABUF(dyi, 1);

        #pragma unroll
        for (int ks = 0; ks < 4; ++ks) {
            const int kbyte = ks*32;
            uint32_t bh[8], bl[8];
            #pragma unroll
            for (int np = 0; np < 2; ++np) {
                const int brow = wn*32 + np*16 + b_row_l;
                const uint32_t boff = SWZ((uint32_t)(brow*128 + kbyte + b_col_l));
                ldsm4(wb + boff,         bh[np*4+0], bh[np*4+1], bh[np*4+2], bh[np*4+3]);
                ldsm4(wb + 16384 + boff, bl[np*4+0], bl[np*4+1], bl[np*4+2], bl[np*4+3]);
            }
            #pragma unroll
            for (int msub = 0; msub < 4; ++msub) {
                const int arow = wm*64 + msub*16 + a_row_l + rowoff;
                const uint32_t aoff = SWZ((uint32_t)(arow*128 + kbyte + a_col_l));
                uint32_t ah[4], al[4];
                ldsm4(ahi + aoff, ah[0], ah[1], ah[2], ah[3]);
                ldsm4(alo + aoff, al[0], al[1], al[2], al[3]);
                #pragma unroll
                for (int nsub = 0; nsub < 4; ++nsub) {
                    float* c = acc[msub][nsub];
                    hmma(c, ah[0],ah[1],ah[2],ah[3], bh[nsub*2], bh[nsub*2+1]); // hi*hi
                    hmma(c, ah[0],ah[1],ah[2],ah[3], bl[nsub*2], bl[nsub*2+1]); // hi*lo
                    hmma(c, al[0],al[1],al[2],al[3], bh[nsub*2], bh[nsub*2+1]); // lo*hi
                }
            }
        }
    }

    // ---------------- epilogue: BN + LeakyReLU + mask ----------------
    const int mrow = lane >> 2;
    const int ncol = (lane & 3) << 1;
    #pragma unroll
    for (int msub = 0; msub < 4; ++msub) {
        const int pix0 = r*Ww + col0 + wm*64 + msub*16 + mrow;
        #pragma unroll
        for (int nsub = 0; nsub < 4; ++nsub) {
            const int oc0 = wn*32 + nsub*8 + ncol;
            #pragma unroll
            for (int h = 0; h < 2; ++h) {
                const int pix = pix0 + h*8;
                #pragma unroll
                for (int e = 0; e < 2; ++e) {
                    const int oc = oc0 + e;
                    float y = fmaf(acc[msub][nsub][h*2+e], s_scale[oc], s_shift[oc]);
                    y = (y >= 0.f) ? y : 0.01f * y;
                    const int base = oc*HWSZ + pix;
                    out[base] = y * (float)mask[base];
                }
            }
        }
    }
}

extern "C" void kernel_launch(void* const* d_in, const int* in_sizes, int n_in,
                              void* d_out, int out_size)
{
    const float* x     = (const float*)d_in[0];
    const float* Wt    = (const float*)d_in[1];
    const float* gamma = (const float*)d_in[2];
    const float* beta  = (const float*)d_in[3];
    const float* mean  = (const float*)d_in[4];
    const float* var   = (const float*)d_in[5];
    const int*   mask  = (const int*)d_in[6];
    float*       out   = (float*)d_out;

    cudaFuncSetAttribute(conv_mma, cudaFuncAttributeMaxDynamicSharedMemorySize, SMEM_TOTAL);

    prep_w<<<(NT*KOC*CIN + 255)/256, 256>>>(Wt);
    conv_mma<<<2048, 256, SMEM_TOTAL>>>(x, gamma, beta, mean, var, mask, out);
}

// round 8
// speedup vs baseline: 4.9376x; 1.0322x over previous
#include <cuda_runtime.h>
#include <cuda_bf16.h>
#include <cstdint>

#define Hh 512
#define Ww 512
#define CIN 64
#define KOC 128
#define HWSZ (Hh*Ww)
#define NT 9

#define SWZ(o) ((o) ^ ((((uint32_t)(o))>>3)&0x70))

// ---- dynamic smem layout (per CTA: 84.5 KB -> 2 CTAs/SM) ----
#define SCL    0
#define SHF    512
#define ABASE  1024
#define AROWS  66
#define ABUFSZ (AROWS*128)                       // 8448
#define ABUF(dy,p) (ABASE + ((dy)*2+(p))*ABUFSZ) // 6 buffers: (dy 0..2) x (hi,lo)
#define WBASE  (ABASE + 6*ABUFSZ)                // 51712: hi @ +0, lo @ +16384
#define SMEM_TOTAL (WBASE + 32768)               // 84480

__device__ __align__(16) unsigned char WbHi[NT*16384];
__device__ __align__(16) unsigned char WbLo[NT*16384];

static __device__ __forceinline__ uint32_t s2u(const void* p){
    uint32_t a;
    asm("{ .reg .u64 t; cvta.to.shared.u64 t, %1; cvt.u32.u64 %0, t; }":"=r"(a):"l"(p));
    return a;
}
static __device__ __forceinline__ void ldsm4(uint32_t addr,
        uint32_t &r0, uint32_t &r1, uint32_t &r2, uint32_t &r3){
    asm volatile("ldmatrix.sync.aligned.m8n8.x4.shared.b16 {%0,%1,%2,%3}, [%4];"
        : "=r"(r0),"=r"(r1),"=r"(r2),"=r"(r3) : "r"(addr));
}
static __device__ __forceinline__ void hmma(float* c,
        uint32_t a0,uint32_t a1,uint32_t a2,uint32_t a3,
        uint32_t b0,uint32_t b1){
    asm volatile("mma.sync.aligned.m16n8k16.row.col.f32.bf16.bf16.f32 "
        "{%0,%1,%2,%3}, {%4,%5,%6,%7}, {%8,%9}, {%0,%1,%2,%3};"
        : "+f"(c[0]),"+f"(c[1]),"+f"(c[2]),"+f"(c[3])
        : "r"(a0),"r"(a1),"r"(a2),"r"(a3),"r"(b0),"r"(b1));
}
static __device__ __forceinline__ void cpasync16(uint32_t daddr, const void* g){
    asm volatile("cp.async.cg.shared.global [%0], [%1], 16;" :: "r"(daddr), "l"(g) : "memory");
}
static __device__ __forceinline__ void cpcommit(){
    asm volatile("cp.async.commit_group;" ::: "memory");
}
template<int N> static __device__ __forceinline__ void cpwait(){
    asm volatile("cp.async.wait_group %0;" :: "n"(N) : "memory");
}

// ---------- prep: split W into bf16 hi/lo, pre-swizzled K-major SW128 tiles ----------
__global__ void prep_w(const float* __restrict__ Wt){
    int idx = blockIdx.x * blockDim.x + threadIdx.x;   // 9*128*64
    if (idx >= NT*KOC*CIN) return;
    int t   = idx >> 13;
    int rem = idx & 8191;
    int n   = rem >> 6;
    int kk  = rem & 63;
    float v = Wt[(n*CIN + kk)*9 + t];
    __nv_bfloat16 hi = __float2bfloat16_rn(v);
    __nv_bfloat16 lo = __float2bfloat16_rn(v - __bfloat162float(hi));
    uint32_t off = SWZ((uint32_t)(n*128 + kk*2));
    *(__nv_bfloat16*)(WbHi + t*16384 + off) = hi;
    *(__nv_bfloat16*)(WbLo + t*16384 + off) = lo;
}

// ---------- main fused kernel: M=64 tile, 2 CTAs/SM ----------
__global__ void __launch_bounds__(256,2)
conv_mma(const float* __restrict__ x,
         const float* __restrict__ gamma, const float* __restrict__ beta,
         const float* __restrict__ mean,  const float* __restrict__ var,
         const int*   __restrict__ mask,  float* __restrict__ out)
{
    extern __shared__ __align__(1024) char sm[];
    const uint32_t smb = s2u(sm);

    const int tid  = threadIdx.x;
    const int w    = tid >> 5;
    const int lane = tid & 31;
    const int wm   = w >> 2;           // 0..1 : m offset wm*32
    const int wn   = w & 3;            // 0..3 : n offset wn*32

    float* s_scale = (float*)(sm + SCL);
    float* s_shift = (float*)(sm + SHF);
    if (tid < KOC) {
        float sc = gamma[tid] * rsqrtf(var[tid] + 1e-5f);
        s_scale[tid] = sc;
        s_shift[tid] = beta[tid] - mean[tid] * sc;
    }

    const int bid  = blockIdx.x;       // 4096
    const int r    = bid >> 3;         // image row
    const int col0 = (bid & 7) * 64;   // 64-col tile

    float acc[2][4][4];
    #pragma unroll
    for (int m = 0; m < 2; ++m)
        #pragma unroll
        for (int n = 0; n < 4; ++n)
            #pragma unroll
            for (int e = 0; e < 4; ++e) acc[m][n][e] = 0.f;

    // ldmatrix lane geometry
    const int jj = lane >> 3, rr = lane & 7;
    const int a_row_l = ((jj & 1) << 3) + rr;
    const int a_col_l = (jj >> 1) << 4;
    const int b_row_l = ((jj >> 1) << 3) + rr;
    const int b_col_l = (jj & 1) << 4;

    // ---- prologue: async-prefetch W tap 0 ----
    {
        const uint32_t d = smb + WBASE;
        #pragma unroll
        for (int p = 0; p < 4; ++p) {
            cpasync16(d + (tid + p*256)*16,         (const char*)WbHi + (tid + p*256)*16);
            cpasync16(d + 16384 + (tid + p*256)*16, (const char*)WbLo + (tid + p*256)*16);
        }
        cpcommit();
    }

    // ---- persistent A: buffer row i <-> image column col0-1+i, i in [0,66) ----
    #pragma unroll
    for (int dy = 0; dy < 3; ++dy) {
        int srow = r + dy - 1;
        srow = (srow < 0) ? -srow : ((srow > Hh-1) ? (2*Hh-2 - srow) : srow);
        const float* xrow = x + (size_t)srow * Ww;
        #pragma unroll
        for (int ii = 0; ii < 3; ++ii) {
            const int ipix = lane + 32*ii;
            if (ipix < AROWS) {
                int cc = col0 - 1 + ipix;
                cc = (cc < 0) ? -cc : ((cc > Ww-1) ? (2*Ww-2 - cc) : cc);
                float v[8];
                #pragma unroll
                for (int j = 0; j < 8; ++j)
                    v[j] = __ldg(xrow + (size_t)(w*8 + j) * HWSZ + cc);
                uint32_t hw4[4], lw4[4];
                #pragma unroll
                for (int q = 0; q < 4; ++q) {
                    float a = v[2*q], b = v[2*q+1];
                    __nv_bfloat162 hp = __floats2bfloat162_rn(a, b);
                    float ra = a - __bfloat162float(hp.x);
                    float rb = b - __bfloat162float(hp.y);
                    __nv_bfloat162 lp = __floats2bfloat162_rn(ra, rb);
                    hw4[q] = *(uint32_t*)&hp;
                    lw4[q] = *(uint32_t*)&lp;
                }
                const uint32_t off = SWZ((uint32_t)(ipix*128 + w*16));
                *(uint4*)(sm + ABUF(dy,0) + off) = make_uint4(hw4[0],hw4[1],hw4[2],hw4[3]);
                *(uint4*)(sm + ABUF(dy,1) + off) = make_uint4(lw4[0],lw4[1],lw4[2],lw4[3]);
            }
        }
    }

    // ---- main loop over 9 taps, single W buffer (peer CTA hides the stalls) ----
    for (int ch = 0; ch < NT; ++ch) {
        cpwait<0>();         // W(ch) landed
        __syncthreads();     // W(ch) + (at ch=0) A staging visible to all warps

        const int dyi    = ch / 3;
        const int rowoff = (ch % 3);         // dx+1
        const uint32_t wb  = smb + WBASE;
        const uint32_t ahi = smb + ABUF(dyi, 0);
        const uint32_t alo = smb + ABUF(dyi, 1);

        #pragma unroll
        for (int ks = 0; ks < 4; ++ks) {
            const int kbyte = ks*32;
            uint32_t bh[8], bl[8];
            #pragma unroll
            for (int np = 0; np < 2; ++np) {
                const int brow = wn*32 + np*16 + b_row_l;
                const uint32_t boff = SWZ((uint32_t)(brow*128 + kbyte + b_col_l));
                ldsm4(wb + boff,         bh[np*4+0], bh[np*4+1], bh[np*4+2], bh[np*4+3]);
                ldsm4(wb + 16384 + boff, bl[np*4+0], bl[np*4+1], bl[np*4+2], bl[np*4+3]);
            }
            #pragma unroll
            for (int msub = 0; msub < 2; ++msub) {
                const int arow = wm*32 + msub*16 + a_row_l + rowoff;
                const uint32_t aoff = SWZ((uint32_t)(arow*128 + kbyte + a_col_l));
                uint32_t ah[4], al[4];
                ldsm4(ahi + aoff, ah[0], ah[1], ah[2], ah[3]);
                ldsm4(alo + aoff, al[0], al[1], al[2], al[3]);
                #pragma unroll
                for (int nsub = 0; nsub < 4; ++nsub) {
                    float* c = acc[msub][nsub];
                    hmma(c, ah[0],ah[1],ah[2],ah[3], bh[nsub*2], bh[nsub*2+1]); // hi*hi
                    hmma(c, ah[0],ah[1],ah[2],ah[3], bl[nsub*2], bl[nsub*2+1]); // hi*lo
                    hmma(c, al[0],al[1],al[2],al[3], bh[nsub*2], bh[nsub*2+1]); // lo*hi
                }
            }
        }

        __syncthreads();     // all warps done reading W(ch) before overwrite
        if (ch + 1 < NT) {
            const uint32_t d = smb + WBASE;
            const char* sh = (const char*)WbHi + (ch+1)*16384;
            const char* sl = (const char*)WbLo + (ch+1)*16384;
            #pragma unroll
            for (int p = 0; p < 4; ++p) {
                cpasync16(d + (tid + p*256)*16,         sh + (tid + p*256)*16);
                cpasync16(d + 16384 + (tid + p*256)*16, sl + (tid + p*256)*16);
            }
            cpcommit();
        }
    }

    // ---------------- epilogue: BN + LeakyReLU + mask ----------------
    const int mrow = lane >> 2;
    const int ncol = (lane & 3) << 1;
    #pragma unroll
    for (int msub = 0; msub < 2; ++msub) {
        const int pix0 = r*Ww + col0 + wm*32 + msub*16 + mrow;
        #pragma unroll
        for (int nsub = 0; nsub < 4; ++nsub) {
            const int oc0 = wn*32 + nsub*8 + ncol;
            #pragma unroll
            for (int h = 0; h < 2; ++h) {
                const int pix = pix0 + h*8;
                #pragma unroll
                for (int e = 0; e < 2; ++e) {
                    const int oc = oc0 + e;
                    float y = fmaf(acc[msub][nsub][h*2+e], s_scale[oc], s_shift[oc]);
                    y = (y >= 0.f) ? y : 0.01f * y;
                    const int base = oc*HWSZ + pix;
                    out[base] = y * (float)mask[base];
                }
            }
        }
    }
}

extern "C" void kernel_launch(void* const* d_in, const int* in_sizes, int n_in,
                              void* d_out, int out_size)
{
    const float* x     = (const float*)d_in[0];
    const float* Wt    = (const float*)d_in[1];
    const float* gamma = (const float*)d_in[2];
    const float* beta  = (const float*)d_in[3];
    const float* mean  = (const float*)d_in[4];
    const float* var   = (const float*)d_in[5];
    const int*   mask  = (const int*)d_in[6];
    float*       out   = (float*)d_out;

    cudaFuncSetAttribute(conv_mma, cudaFuncAttributeMaxDynamicSharedMemorySize, SMEM_TOTAL);

    prep_w<<<(NT*KOC*CIN + 255)/256, 256>>>(Wt);
    conv_mma<<<4096, 256, SMEM_TOTAL>>>(x, gamma, beta, mean, var, mask, out);
}

// round 9
// speedup vs baseline: 10.8224x; 2.1919x over previous
#include <cuda_runtime.h>
#include <cuda_fp16.h>
#include <cstdint>

#define Hh 512
#define Ww 512
#define CIN 64
#define KOC 128
#define HWSZ (Hh*Ww)
#define NT 9

#define SWZ(o) ((o) ^ ((((uint32_t)(o))>>3)&0x70))

// ---- dynamic smem layout (84 KB -> 2 CTAs/SM) ----
#define SCL    0
#define SHF    512
#define ABASE  1024
#define AROWS  136
#define ABUFSZ (AROWS*128)                   // 17408
#define ABUF(dy) (ABASE + (dy)*ABUFSZ)       // 3 buffers (dy 0..2), fp16
#define WBASE  (ABASE + 3*ABUFSZ)            // 53248
#define WBUF(b) (WBASE + (b)*16384)          // double-buffered W, fp16
#define SMEM_TOTAL (WBASE + 2*16384)         // 86016

__device__ __align__(16) unsigned char Wb[NT*16384];   // pre-swizzled fp16 W tiles

static __device__ __forceinline__ uint32_t s2u(const void* p){
    uint32_t a;
    asm("{ .reg .u64 t; cvta.to.shared.u64 t, %1; cvt.u32.u64 %0, t; }":"=r"(a):"l"(p));
    return a;
}
static __device__ __forceinline__ void ldsm4(uint32_t addr,
        uint32_t &r0, uint32_t &r1, uint32_t &r2, uint32_t &r3){
    asm volatile("ldmatrix.sync.aligned.m8n8.x4.shared.b16 {%0,%1,%2,%3}, [%4];"
        : "=r"(r0),"=r"(r1),"=r"(r2),"=r"(r3) : "r"(addr));
}
static __device__ __forceinline__ void hmma(float* c,
        uint32_t a0,uint32_t a1,uint32_t a2,uint32_t a3,
        uint32_t b0,uint32_t b1){
    asm volatile("mma.sync.aligned.m16n8k16.row.col.f32.f16.f16.f32 "
        "{%0,%1,%2,%3}, {%4,%5,%6,%7}, {%8,%9}, {%0,%1,%2,%3};"
        : "+f"(c[0]),"+f"(c[1]),"+f"(c[2]),"+f"(c[3])
        : "r"(a0),"r"(a1),"r"(a2),"r"(a3),"r"(b0),"r"(b1));
}
static __device__ __forceinline__ void cpasync16(uint32_t daddr, const void* g){
    asm volatile("cp.async.cg.shared.global [%0], [%1], 16;" :: "r"(daddr), "l"(g) : "memory");
}
static __device__ __forceinline__ void cpcommit(){
    asm volatile("cp.async.commit_group;" ::: "memory");
}
template<int N> static __device__ __forceinline__ void cpwait(){
    asm volatile("cp.async.wait_group %0;" :: "n"(N) : "memory");
}

// ---------- prep: W -> fp16, pre-swizzled K-major SW128 tiles ----------
__global__ void prep_w(const float* __restrict__ Wt){
    int idx = blockIdx.x * blockDim.x + threadIdx.x;   // 9*128*64
    if (idx >= NT*KOC*CIN) return;
    int t   = idx >> 13;
    int rem = idx & 8191;
    int n   = rem >> 6;
    int kk  = rem & 63;
    float v = Wt[(n*CIN + kk)*9 + t];
    uint32_t off = SWZ((uint32_t)(n*128 + kk*2));
    *(__half*)(Wb + t*16384 + off) = __float2half_rn(v);
}

// ---------- main fused kernel: single-pass fp16, M=128 x N=128, 2 CTAs/SM ----------
__global__ void __launch_bounds__(256,2)
conv_mma_f16(const float* __restrict__ x,
             const float* __restrict__ gamma, const float* __restrict__ beta,
             const float* __restrict__ mean,  const float* __restrict__ var,
             const int*   __restrict__ mask,  float* __restrict__ out)
{
    extern __shared__ __align__(1024) char sm[];
    const uint32_t smb = s2u(sm);

    const int tid  = threadIdx.x;
    const int w    = tid >> 5;
    const int lane = tid & 31;
    const int wm   = w >> 2;           // 0..1 : m offset wm*64
    const int wn   = w & 3;            // 0..3 : n offset wn*32

    float* s_scale = (float*)(sm + SCL);
    float* s_shift = (float*)(sm + SHF);
    if (tid < KOC) {
        float sc = gamma[tid] * rsqrtf(var[tid] + 1e-5f);
        s_scale[tid] = sc;
        s_shift[tid] = beta[tid] - mean[tid] * sc;
    }

    const int bid  = blockIdx.x;       // 2048
    const int r    = bid >> 2;         // image row
    const int col0 = (bid & 3) * 128;  // 128-col tile

    float acc[4][4][4];
    #pragma unroll
    for (int m = 0; m < 4; ++m)
        #pragma unroll
        for (int n = 0; n < 4; ++n)
            #pragma unroll
            for (int e = 0; e < 4; ++e) acc[m][n][e] = 0.f;

    // ldmatrix lane geometry
    const int jj = lane >> 3, rr = lane & 7;
    const int a_row_l = ((jj & 1) << 3) + rr;
    const int a_col_l = (jj >> 1) << 4;
    const int b_row_l = ((jj >> 1) << 3) + rr;
    const int b_col_l = (jj & 1) << 4;

    // ---- prologue: async-prefetch W tap 0 ----
    {
        const uint32_t d = smb + WBUF(0);
        #pragma unroll
        for (int p = 0; p < 4; ++p)
            cpasync16(d + (tid + p*256)*16, (const char*)Wb + (tid + p*256)*16);
        cpcommit();
    }

    // ---- persistent A (fp16): buffer row i <-> image column col0-1+i, i in [0,130) ----
    #pragma unroll
    for (int dy = 0; dy < 3; ++dy) {
        int srow = r + dy - 1;
        srow = (srow < 0) ? -srow : ((srow > Hh-1) ? (2*Hh-2 - srow) : srow);
        const float* xrow = x + (size_t)srow * Ww;
        #pragma unroll
        for (int ii = 0; ii < 5; ++ii) {
            const int ipix = lane + 32*ii;
            if (ipix < 130) {
                int cc = col0 - 1 + ipix;
                cc = (cc < 0) ? -cc : ((cc > Ww-1) ? (2*Ww-2 - cc) : cc);
                float v[8];
                #pragma unroll
                for (int j = 0; j < 8; ++j)
                    v[j] = __ldg(xrow + (size_t)(w*8 + j) * HWSZ + cc);
                uint32_t hw4[4];
                #pragma unroll
                for (int q = 0; q < 4; ++q) {
                    __half2 hp = __floats2half2_rn(v[2*q], v[2*q+1]);
                    hw4[q] = *(uint32_t*)&hp;
                }
                const uint32_t off = SWZ((uint32_t)(ipix*128 + w*16));
                *(uint4*)(sm + ABUF(dy) + off) = make_uint4(hw4[0],hw4[1],hw4[2],hw4[3]);
            }
        }
    }

    // ---- main loop over 9 taps, W double-buffered via cp.async ----
    for (int ch = 0; ch < NT; ++ch) {
        __syncthreads();     // all reads of WBUF((ch+1)&1) from tap ch-1 complete

        if (ch + 1 < NT) {   // prefetch W(ch+1) into the other buffer
            const uint32_t d = smb + WBUF((ch+1) & 1);
            const char* sh = (const char*)Wb + (ch+1)*16384;
            #pragma unroll
            for (int p = 0; p < 4; ++p)
                cpasync16(d + (tid + p*256)*16, sh + (tid + p*256)*16);
            cpcommit();
            cpwait<1>();     // W(ch) has landed
        } else {
            cpwait<0>();
        }
        __syncthreads();     // W(ch) (+ A staging at ch=0) visible to all warps

        const int dyi    = ch / 3;
        const int rowoff = (ch % 3);         // dx+1
        const uint32_t wb = smb + WBUF(ch & 1);
        const uint32_t ab = smb + ABUF(dyi);

        #pragma unroll
        for (int ks = 0; ks < 4; ++ks) {
            const int kbyte = ks*32;
            uint32_t bh[8];
            #pragma unroll
            for (int np = 0; np < 2; ++np) {
                const int brow = wn*32 + np*16 + b_row_l;
                const uint32_t boff = SWZ((uint32_t)(brow*128 + kbyte + b_col_l));
                ldsm4(wb + boff, bh[np*4+0], bh[np*4+1], bh[np*4+2], bh[np*4+3]);
            }
            #pragma unroll
            for (int msub = 0; msub < 4; ++msub) {
                const int arow = wm*64 + msub*16 + a_row_l + rowoff;
                const uint32_t aoff = SWZ((uint32_t)(arow*128 + kbyte + a_col_l));
                uint32_t ah[4];
                ldsm4(ab + aoff, ah[0], ah[1], ah[2], ah[3]);
                #pragma unroll
                for (int nsub = 0; nsub < 4; ++nsub)
                    hmma(acc[msub][nsub], ah[0],ah[1],ah[2],ah[3],
                         bh[nsub*2], bh[nsub*2+1]);
            }
        }
    }

    // ---------------- epilogue: BN + LeakyReLU + mask ----------------
    const int mrow = lane >> 2;
    const int ncol = (lane & 3) << 1;
    #pragma unroll
    for (int msub = 0; msub < 4; ++msub) {
        const int pix0 = r*Ww + col0 + wm*64 + msub*16 + mrow;
        #pragma unroll
        for (int nsub = 0; nsub < 4; ++nsub) {
            const int oc0 = wn*32 + nsub*8 + ncol;
            #pragma unroll
            for (int h = 0; h < 2; ++h) {
                const int pix = pix0 + h*8;
                #pragma unroll
                for (int e = 0; e < 2; ++e) {
                    const int oc = oc0 + e;
                    float y = fmaf(acc[msub][nsub][h*2+e], s_scale[oc], s_shift[oc]);
                    y = (y >= 0.f) ? y : 0.01f * y;
                    const int base = oc*HWSZ + pix;
                    out[base] = y * (float)mask[base];
                }
            }
        }
    }
}

extern "C" void kernel_launch(void* const* d_in, const int* in_sizes, int n_in,
                              void* d_out, int out_size)
{
    const float* x     = (const float*)d_in[0];
    const float* Wt    = (const float*)d_in[1];
    const float* gamma = (const float*)d_in[2];
    const float* beta  = (const float*)d_in[3];
    const float* mean  = (const float*)d_in[4];
    const float* var   = (const float*)d_in[5];
    const int*   mask  = (const int*)d_in[6];
    float*       out   = (float*)d_out;

    cudaFuncSetAttribute(conv_mma_f16, cudaFuncAttributeMaxDynamicSharedMemorySize, SMEM_TOTAL);

    prep_w<<<(NT*KOC*CIN + 255)/256, 256>>>(Wt);
    conv_mma_f16<<<2048, 256, SMEM_TOTAL>>>(x, gamma, beta, mean, var, mask, out);
}